// round 4
// baseline (speedup 1.0000x reference)
#include <cuda_runtime.h>

// ---------------------------------------------------------------------------
// 5-layer stacked LSTM, H=51, B=256, T=2048. Output depends only on layer-3 h
// => layers 4,5 dead. 3 roles (L1,L2,L3) x 32 batch groups = 96 CTAs.
// Row-pair split: thread (j,p): p=0 input GEMV + bias, p=1 recurrent GEMV.
// 448 threads = 13 compute warps + 1 comm warp. f32x2 packed FMA, pair
// reduction via shfl.xor, register-resident weights, double-buffered xin.
// ---------------------------------------------------------------------------

#define HN 51
#define NJ 204
#define TN 2048
#define NG 32
#define BT 8
#define NSLOT 8
#define NTH 448
#define COMM0 416            // first lane of comm warp (warp 13)

typedef unsigned long long ull;

__device__ float    g_hbuf[2][NG][NSLOT][HN * BT];
__device__ unsigned g_prod[2][NG];
__device__ unsigned g_cons[2][NG];

__device__ __forceinline__ unsigned ld_acq(const unsigned* p) {
    unsigned v;
    asm volatile("ld.global.acquire.gpu.u32 %0, [%1];" : "=r"(v) : "l"(p));
    return v;
}
__device__ __forceinline__ void st_rel(unsigned* p, unsigned v) {
    asm volatile("st.global.release.gpu.u32 [%0], %1;" :: "l"(p), "r"(v));
}
__device__ __forceinline__ void wait_ge(unsigned* p, unsigned v) {
    while (ld_acq(p) < v) { }
}
__device__ __forceinline__ float ldcg(const float* p) {
    float v;
    asm volatile("ld.global.cg.f32 %0, [%1];" : "=f"(v) : "l"(p));
    return v;
}
__device__ __forceinline__ ull ffma2(ull a, ull b, ull c) {
    ull d;
    asm("fma.rn.f32x2 %0, %1, %2, %3;" : "=l"(d) : "l"(a), "l"(b), "l"(c));
    return d;
}
__device__ __forceinline__ ull splat2(float x) {
    ull d; unsigned u = __float_as_uint(x);
    asm("mov.b64 %0, {%1, %2};" : "=l"(d) : "r"(u), "r"(u));
    return d;
}
__device__ __forceinline__ float2 unpack2(ull v) {
    float2 f;
    asm("mov.b64 {%0, %1}, %2;" : "=f"(f.x), "=f"(f.y) : "l"(v));
    return f;
}
__device__ __forceinline__ float sigf(float x) {
    return __fdividef(1.f, 1.f + __expf(-x));
}
__device__ __forceinline__ float tanhfast(float x) {
    return 2.f * __fdividef(1.f, 1.f + __expf(-2.f * x)) - 1.f;
}

__global__ void __launch_bounds__(64, 1) reset_kernel() {
    int i = threadIdx.x;
    if (i < NG) {
        g_prod[0][i] = 0; g_prod[1][i] = 0;
        g_cons[0][i] = 0; g_cons[1][i] = 0;
    }
}

__global__ void __launch_bounds__(NTH, 1) lstm_kernel(
    const float* __restrict__ x,    const float* __restrict__ Wih1,
    const float* __restrict__ Whh1, const float* __restrict__ bih1,
    const float* __restrict__ bhh1, const float* __restrict__ Wih,
    const float* __restrict__ Whh,  const float* __restrict__ bih,
    const float* __restrict__ bhh,  const float* __restrict__ Wl,
    const float* __restrict__ bl,   float* __restrict__ out)
{
    __shared__ __align__(16) float xin[2][HN * BT];   // layer input double buffer
    __shared__ __align__(16) float h_t[HN * BT];      // [k][b]
    __shared__ __align__(16) float c_s[HN * BT];
    __shared__ __align__(16) float gates[4 * HN * BT]; // [j][b]
    __shared__ __align__(16) float xchunk[32 * BT];   // [q][b], L1 raw-x prefetch
    __shared__ float wl_s[52];

    const int tid  = threadIdx.x;
    const int role = blockIdx.x / NG;   // 0=L1, 1=L2, 2=L3
    const int g    = blockIdx.x % NG;
    const int j    = tid >> 1;          // gate row (valid if < 204)
    const int p    = tid & 1;           // 0: input GEMV+bias, 1: recurrent GEMV
    const int jj   = (j < NJ) ? j : (NJ - 1);   // clamped for safe weight loads
    const bool is_comm = (tid >= COMM0);

    // ---------------- per-thread register weights ----------------
    float w_r[HN];
    ull bias2 = 0, w1_2 = 0;
    if (!is_comm) {
        if (role == 0) {
            if (p == 1) {
                #pragma unroll
                for (int k = 0; k < HN; k++) w_r[k] = Whh1[jj * HN + k];
            } else {
                bias2 = splat2(bih1[jj] + bhh1[jj]);
                w1_2  = splat2(Wih1[jj]);
            }
        } else {
            const int l = role - 1;
            if (p == 1) {
                #pragma unroll
                for (int k = 0; k < HN; k++) w_r[k] = Whh[(l * NJ + jj) * HN + k];
            } else {
                #pragma unroll
                for (int k = 0; k < HN; k++) w_r[k] = Wih[(l * NJ + jj) * HN + k];
                bias2 = splat2(bih[l * NJ + jj] + bhh[l * NJ + jj]);
            }
        }
    }
    if (role == 2 && tid < HN) wl_s[tid] = Wl[tid];
    const float blv = (role == 2) ? bl[0] : 0.f;
    for (int i = tid; i < HN * BT; i += NTH) { h_t[i] = 0.f; c_s[i] = 0.f; }
    __syncthreads();

    float*       ring_out = (role < 2) ? &g_hbuf[role][g][0][0]     : (float*)0;
    const float* ring_in  = (role > 0) ? &g_hbuf[role - 1][g][0][0] : (const float*)0;

    // prologue: comm warp fetches slot 0 -> xin[0]
    if (role > 0 && is_comm) {
        if (tid == COMM0) wait_ge(&g_prod[role - 1][g], 1u);
        __syncwarp();
        for (int i = tid - COMM0; i < HN * BT; i += 32) xin[0][i] = ldcg(ring_in + i);
        __syncwarp();
        if (tid == COMM0) st_rel(&g_cons[role - 1][g], 1u);
    }
    __syncthreads();

    for (int t = 0; t < TN; t++) {
        // ---- L1: refill 32-step x chunk (coalesced), transposed [q][b] ----
        if (role == 0 && (t & 31) == 0) {
            if (tid < 256) {
                int b = tid >> 5, q = tid & 31;
                xchunk[q * BT + b] = x[(size_t)(g * BT + b) * TN + t + q];
            }
            __syncthreads();
        }

        // ================= P0: half-GEMVs + comm =================
        if (!is_comm) {
            ull a0, a1, a2, a3;
            if (p == 0) {
                a0 = bias2; a1 = bias2; a2 = bias2; a3 = bias2;
                if (role == 0) {
                    const ulonglong2* xp = (const ulonglong2*)&xchunk[(t & 31) * BT];
                    ulonglong2 X0 = xp[0], X1 = xp[1];
                    a0 = ffma2(X0.x, w1_2, a0); a1 = ffma2(X0.y, w1_2, a1);
                    a2 = ffma2(X1.x, w1_2, a2); a3 = ffma2(X1.y, w1_2, a3);
                } else {
                    const ulonglong2* xp = (const ulonglong2*)&xin[t & 1][0];
                    #pragma unroll
                    for (int k = 0; k < HN; k++) {
                        ulonglong2 X0 = xp[2 * k], X1 = xp[2 * k + 1];
                        ull w2 = splat2(w_r[k]);
                        a0 = ffma2(X0.x, w2, a0); a1 = ffma2(X0.y, w2, a1);
                        a2 = ffma2(X1.x, w2, a2); a3 = ffma2(X1.y, w2, a3);
                    }
                }
            } else {
                a0 = 0; a1 = 0; a2 = 0; a3 = 0;
                const ulonglong2* hp = (const ulonglong2*)h_t;
                #pragma unroll
                for (int k = 0; k < HN; k++) {
                    ulonglong2 H0 = hp[2 * k], H1 = hp[2 * k + 1];
                    ull w2 = splat2(w_r[k]);
                    a0 = ffma2(H0.x, w2, a0); a1 = ffma2(H0.y, w2, a1);
                    a2 = ffma2(H1.x, w2, a2); a3 = ffma2(H1.y, w2, a3);
                }
            }
            // pair reduction: lanes (2r, 2r+1) hold the two halves
            float2 f0 = unpack2(a0), f1 = unpack2(a1), f2 = unpack2(a2), f3 = unpack2(a3);
            float r[8] = { f0.x, f0.y, f1.x, f1.y, f2.x, f2.y, f3.x, f3.y };
            #pragma unroll
            for (int i = 0; i < 8; i++)
                r[i] += __shfl_xor_sync(0xffffffffu, r[i], 1);
            if (j < NJ) {
                // p=0 stores batches 0-3, p=1 stores batches 4-7 (one STS.128 each)
                float4 v;
                v.x = r[4 * p + 0]; v.y = r[4 * p + 1];
                v.z = r[4 * p + 2]; v.w = r[4 * p + 3];
                *(float4*)&gates[j * BT + 4 * p] = v;
            }
        } else {
            // comm warp: prefetch next xin, backpressure, (L3) output projection
            if (role > 0 && t + 1 < TN) {
                if (tid == COMM0) wait_ge(&g_prod[role - 1][g], (unsigned)(t + 2));
                __syncwarp();
                const float* src = ring_in + ((t + 1) & (NSLOT - 1)) * HN * BT;
                float* dst = xin[(t + 1) & 1];
                for (int i = tid - COMM0; i < HN * BT; i += 32) dst[i] = ldcg(src + i);
                __syncwarp();
                if (tid == COMM0) st_rel(&g_cons[role - 1][g], (unsigned)(t + 2));
            }
            if (role < 2 && t >= NSLOT && tid == COMM0)
                wait_ge(&g_cons[role][g], (unsigned)(t - (NSLOT - 1)));
            if (role == 2 && t > 0) {
                int b = tid - COMM0;
                if (b < BT) {
                    float a = blv;
                    #pragma unroll
                    for (int u = 0; u < HN; u++) a += h_t[u * BT + b] * wl_s[u];
                    out[(size_t)(g * BT + b) * TN + (t - 1)] = a;
                }
            }
        }
        __syncthreads();   // gates ready; h_t free; backpressure cleared

        // ================= P1: cell update =================
        if (tid < HN * BT) {
            const int i = tid;
            float gi = gates[i];
            float gf = gates[HN * BT + i];
            float gg = gates[2 * HN * BT + i];
            float go = gates[3 * HN * BT + i];
            float c  = sigf(gf) * c_s[i] + sigf(gi) * tanhfast(gg);
            float h  = sigf(go) * tanhfast(c);
            c_s[i] = c;
            h_t[i] = h;
            if (role < 2) ring_out[(t & (NSLOT - 1)) * HN * BT + i] = h;
        }
        __syncthreads();   // h_t / ring slot complete
        if (role < 2 && tid == 0) st_rel(&g_prod[role][g], (unsigned)(t + 1));
    }

    // epilogue: out for t = TN-1 (from final h_t of layer 3)
    if (role == 2 && tid < BT) {
        float a = blv;
        #pragma unroll
        for (int u = 0; u < HN; u++) a += h_t[u * BT + tid] * wl_s[u];
        out[(size_t)(g * BT + tid) * TN + (TN - 1)] = a;
    }
}

extern "C" void kernel_launch(void* const* d_in, const int* in_sizes, int n_in,
                              void* d_out, int out_size)
{
    (void)in_sizes; (void)n_in; (void)out_size;
    const float* x    = (const float*)d_in[0];
    const float* Wih1 = (const float*)d_in[1];
    const float* Whh1 = (const float*)d_in[2];
    const float* bih1 = (const float*)d_in[3];
    const float* bhh1 = (const float*)d_in[4];
    const float* Wih  = (const float*)d_in[5];
    const float* Whh  = (const float*)d_in[6];
    const float* bih  = (const float*)d_in[7];
    const float* bhh  = (const float*)d_in[8];
    const float* Wl   = (const float*)d_in[9];
    const float* bl   = (const float*)d_in[10];
    float* out = (float*)d_out;

    reset_kernel<<<1, 64>>>();
    lstm_kernel<<<3 * NG, NTH>>>(x, Wih1, Whh1, bih1, bhh1,
                                 Wih, Whh, bih, bhh, Wl, bl, out);
}

// round 5
// speedup vs baseline: 1.2193x; 1.2193x over previous
#include <cuda_runtime.h>

// ---------------------------------------------------------------------------
// 5-layer stacked LSTM, H=51, B=256, T=2048. Output depends only on layer-3 h
// => layers 4,5 dead. 3 roles (L1,L2,L3) x 32 batch groups = 96 CTAs.
// WARP-granular GEMV split (no divergence): warps 0-6 input GEMV -> gates0,
// warps 7-13 recurrent GEMV -> gates1, warp 14 = comm. Halves summed in the
// cell update. f32x2 packed FMA, register-resident weights, double-buffered xin.
// ---------------------------------------------------------------------------

#define HN 51
#define NJ 204
#define TN 2048
#define NG 32
#define BT 8
#define NSLOT 8
#define NTH 480
#define P1_0 224             // first tid of recurrent-GEMV half
#define COMM0 448            // first tid of comm warp (warp 14)

typedef unsigned long long ull;

__device__ float    g_hbuf[2][NG][NSLOT][HN * BT];
__device__ unsigned g_prod[2][NG];
__device__ unsigned g_cons[2][NG];

__device__ __forceinline__ unsigned ld_acq(const unsigned* p) {
    unsigned v;
    asm volatile("ld.global.acquire.gpu.u32 %0, [%1];" : "=r"(v) : "l"(p));
    return v;
}
__device__ __forceinline__ void st_rel(unsigned* p, unsigned v) {
    asm volatile("st.global.release.gpu.u32 [%0], %1;" :: "l"(p), "r"(v));
}
__device__ __forceinline__ void wait_ge(unsigned* p, unsigned v) {
    while (ld_acq(p) < v) { }
}
__device__ __forceinline__ float ldcg(const float* p) {
    float v;
    asm volatile("ld.global.cg.f32 %0, [%1];" : "=f"(v) : "l"(p));
    return v;
}
__device__ __forceinline__ ull ffma2(ull a, ull b, ull c) {
    ull d;
    asm("fma.rn.f32x2 %0, %1, %2, %3;" : "=l"(d) : "l"(a), "l"(b), "l"(c));
    return d;
}
__device__ __forceinline__ ull splat2(float x) {
    ull d; unsigned u = __float_as_uint(x);
    asm("mov.b64 %0, {%1, %2};" : "=l"(d) : "r"(u), "r"(u));
    return d;
}
__device__ __forceinline__ float sigf(float x) {
    return __fdividef(1.f, 1.f + __expf(-x));
}
__device__ __forceinline__ float tanhfast(float x) {
    return 2.f * __fdividef(1.f, 1.f + __expf(-2.f * x)) - 1.f;
}

__global__ void __launch_bounds__(64, 1) reset_kernel() {
    int i = threadIdx.x;
    if (i < NG) {
        g_prod[0][i] = 0; g_prod[1][i] = 0;
        g_cons[0][i] = 0; g_cons[1][i] = 0;
    }
}

__global__ void __launch_bounds__(NTH, 1) lstm_kernel(
    const float* __restrict__ x,    const float* __restrict__ Wih1,
    const float* __restrict__ Whh1, const float* __restrict__ bih1,
    const float* __restrict__ bhh1, const float* __restrict__ Wih,
    const float* __restrict__ Whh,  const float* __restrict__ bih,
    const float* __restrict__ bhh,  const float* __restrict__ Wl,
    const float* __restrict__ bl,   float* __restrict__ out)
{
    __shared__ __align__(16) float xin[2][HN * BT];     // layer input double buffer
    __shared__ __align__(16) float h_t[HN * BT];        // [k][b]
    __shared__ __align__(16) float c_s[HN * BT];
    __shared__ __align__(16) float gates0[NJ * BT];     // input-GEMV half (+bias)
    __shared__ __align__(16) float gates1[NJ * BT];     // recurrent-GEMV half
    __shared__ __align__(16) float xchunk[32 * BT];     // [q][b], L1 raw-x prefetch
    __shared__ float wl_s[52];

    const int tid  = threadIdx.x;
    const int role = blockIdx.x / NG;   // 0=L1, 1=L2, 2=L3
    const int g    = blockIdx.x % NG;

    const bool is_p0   = (tid < P1_0);                  // warps 0-6
    const bool is_comm = (tid >= COMM0);                // warp 14
    const int  jraw    = is_p0 ? tid : (tid - P1_0);    // row index within half
    const bool active  = (!is_comm) && (jraw < NJ);
    const int  j       = active ? jraw : 0;             // clamped

    // ---------------- per-thread register weights ----------------
    float w_r[HN];
    ull bias2 = 0, w1_2 = 0;
    if (active) {
        if (role == 0) {
            if (is_p0) {
                bias2 = splat2(bih1[j] + bhh1[j]);
                w1_2  = splat2(Wih1[j]);
            } else {
                #pragma unroll
                for (int k = 0; k < HN; k++) w_r[k] = Whh1[j * HN + k];
            }
        } else {
            const int l = role - 1;
            if (is_p0) {
                #pragma unroll
                for (int k = 0; k < HN; k++) w_r[k] = Wih[(l * NJ + j) * HN + k];
                bias2 = splat2(bih[l * NJ + j] + bhh[l * NJ + j]);
            } else {
                #pragma unroll
                for (int k = 0; k < HN; k++) w_r[k] = Whh[(l * NJ + j) * HN + k];
            }
        }
    }
    if (role == 2 && tid < HN) wl_s[tid] = Wl[tid];
    const float blv = (role == 2) ? bl[0] : 0.f;
    for (int i = tid; i < HN * BT; i += NTH) { h_t[i] = 0.f; c_s[i] = 0.f; }
    __syncthreads();

    float*       ring_out = (role < 2) ? &g_hbuf[role][g][0][0]     : (float*)0;
    const float* ring_in  = (role > 0) ? &g_hbuf[role - 1][g][0][0] : (const float*)0;

    // prologue: comm warp fetches slot 0 -> xin[0]
    if (role > 0 && is_comm) {
        if (tid == COMM0) wait_ge(&g_prod[role - 1][g], 1u);
        __syncwarp();
        for (int i = tid - COMM0; i < HN * BT; i += 32) xin[0][i] = ldcg(ring_in + i);
        __syncwarp();
        if (tid == COMM0) st_rel(&g_cons[role - 1][g], 1u);
    }
    __syncthreads();

    for (int t = 0; t < TN; t++) {
        // ---- L1: refill 32-step x chunk (coalesced), transposed [q][b] ----
        if (role == 0 && (t & 31) == 0) {
            if (tid < 256) {
                int b = tid >> 5, q = tid & 31;
                xchunk[q * BT + b] = x[(size_t)(g * BT + b) * TN + t + q];
            }
            __syncthreads();
        }

        // ================= P0: half-GEMVs (warp-split) + comm =================
        if (!is_comm) {
            ull a0, a1, a2, a3;
            if (is_p0) {
                a0 = bias2; a1 = bias2; a2 = bias2; a3 = bias2;
                if (role == 0) {
                    const ulonglong2* xp = (const ulonglong2*)&xchunk[(t & 31) * BT];
                    ulonglong2 X0 = xp[0], X1 = xp[1];
                    a0 = ffma2(X0.x, w1_2, a0); a1 = ffma2(X0.y, w1_2, a1);
                    a2 = ffma2(X1.x, w1_2, a2); a3 = ffma2(X1.y, w1_2, a3);
                } else {
                    const ulonglong2* xp = (const ulonglong2*)&xin[t & 1][0];
                    #pragma unroll
                    for (int k = 0; k < HN; k++) {
                        ulonglong2 X0 = xp[2 * k], X1 = xp[2 * k + 1];
                        ull w2 = splat2(w_r[k]);
                        a0 = ffma2(X0.x, w2, a0); a1 = ffma2(X0.y, w2, a1);
                        a2 = ffma2(X1.x, w2, a2); a3 = ffma2(X1.y, w2, a3);
                    }
                }
                if (active) {
                    ulonglong2* gp = (ulonglong2*)gates0;
                    ulonglong2 s0; s0.x = a0; s0.y = a1;
                    ulonglong2 s1; s1.x = a2; s1.y = a3;
                    gp[j * 2 + 0] = s0;
                    gp[j * 2 + 1] = s1;
                }
            } else {
                a0 = 0; a1 = 0; a2 = 0; a3 = 0;
                const ulonglong2* hp = (const ulonglong2*)h_t;
                #pragma unroll
                for (int k = 0; k < HN; k++) {
                    ulonglong2 H0 = hp[2 * k], H1 = hp[2 * k + 1];
                    ull w2 = splat2(w_r[k]);
                    a0 = ffma2(H0.x, w2, a0); a1 = ffma2(H0.y, w2, a1);
                    a2 = ffma2(H1.x, w2, a2); a3 = ffma2(H1.y, w2, a3);
                }
                if (active) {
                    ulonglong2* gp = (ulonglong2*)gates1;
                    ulonglong2 s0; s0.x = a0; s0.y = a1;
                    ulonglong2 s1; s1.x = a2; s1.y = a3;
                    gp[j * 2 + 0] = s0;
                    gp[j * 2 + 1] = s1;
                }
            }
        } else {
            // comm warp: prefetch next xin, backpressure, (L3) output projection
            if (role > 0 && t + 1 < TN) {
                if (tid == COMM0) wait_ge(&g_prod[role - 1][g], (unsigned)(t + 2));
                __syncwarp();
                const float* src = ring_in + ((t + 1) & (NSLOT - 1)) * HN * BT;
                float* dst = xin[(t + 1) & 1];
                for (int i = tid - COMM0; i < HN * BT; i += 32) dst[i] = ldcg(src + i);
                __syncwarp();
                if (tid == COMM0) st_rel(&g_cons[role - 1][g], (unsigned)(t + 2));
            }
            if (role < 2 && t >= NSLOT && tid == COMM0)
                wait_ge(&g_cons[role][g], (unsigned)(t - (NSLOT - 1)));
            if (role == 2 && t > 0) {
                int b = tid - COMM0;
                if (b < BT) {
                    float a = blv;
                    #pragma unroll
                    for (int u = 0; u < HN; u++) a += h_t[u * BT + b] * wl_s[u];
                    out[(size_t)(g * BT + b) * TN + (t - 1)] = a;
                }
            }
        }
        __syncthreads();   // gates ready; h_t free; backpressure cleared

        // ================= P1: cell update (sum the two halves) =================
        if (tid < HN * BT) {
            const int i = tid;
            float gi = gates0[i]            + gates1[i];
            float gf = gates0[HN*BT + i]    + gates1[HN*BT + i];
            float gg = gates0[2*HN*BT + i]  + gates1[2*HN*BT + i];
            float go = gates0[3*HN*BT + i]  + gates1[3*HN*BT + i];
            float c  = sigf(gf) * c_s[i] + sigf(gi) * tanhfast(gg);
            float h  = sigf(go) * tanhfast(c);
            c_s[i] = c;
            h_t[i] = h;
            if (role < 2) ring_out[(t & (NSLOT - 1)) * HN * BT + i] = h;
        }
        __syncthreads();   // h_t / ring slot complete
        if (role < 2 && tid == 0) st_rel(&g_prod[role][g], (unsigned)(t + 1));
    }

    // epilogue: out for t = TN-1 (from final h_t of layer 3)
    if (role == 2 && tid < BT) {
        float a = blv;
        #pragma unroll
        for (int u = 0; u < HN; u++) a += h_t[u * BT + tid] * wl_s[u];
        out[(size_t)(g * BT + tid) * TN + (TN - 1)] = a;
    }
}

extern "C" void kernel_launch(void* const* d_in, const int* in_sizes, int n_in,
                              void* d_out, int out_size)
{
    (void)in_sizes; (void)n_in; (void)out_size;
    const float* x    = (const float*)d_in[0];
    const float* Wih1 = (const float*)d_in[1];
    const float* Whh1 = (const float*)d_in[2];
    const float* bih1 = (const float*)d_in[3];
    const float* bhh1 = (const float*)d_in[4];
    const float* Wih  = (const float*)d_in[5];
    const float* Whh  = (const float*)d_in[6];
    const float* bih  = (const float*)d_in[7];
    const float* bhh  = (const float*)d_in[8];
    const float* Wl   = (const float*)d_in[9];
    const float* bl   = (const float*)d_in[10];
    float* out = (float*)d_out;

    reset_kernel<<<1, 64>>>();
    lstm_kernel<<<3 * NG, NTH>>>(x, Wih1, Whh1, bih1, bhh1,
                                 Wih, Whh, bih, bhh, Wl, bl, out);
}

// round 6
// speedup vs baseline: 1.2776x; 1.0478x over previous
#include <cuda_runtime.h>

// ---------------------------------------------------------------------------
// 5-layer stacked LSTM, H=51, B=256, T=2048. Output depends only on layer-3 h
// => layers 4,5 dead. 3 roles (L1,L2,L3) x 32 batch groups = 96 CTAs.
// Warp-granular GEMV split: warps 0-6 input GEMV -> gates0, warps 7-13
// recurrent GEMV -> gates1, warp 14 = comm. DEEP PREFETCH (D=4): the comm warp
// runs 4 steps ahead of compute; the prologue forces a 4-phase producer lead
// which persists (equal rates), so flag waits ~0 and the L2 copy overlaps
// compute instead of serializing after it.
// ---------------------------------------------------------------------------

#define HN 51
#define NJ 204
#define TN 2048
#define NG 32
#define BT 8
#define NSLOT 16             // ring slots (power of 2)
#define XBUF 8               // xin SMEM slots (power of 2), > DPRE
#define DPRE 4               // prefetch distance
#define NTH 480
#define P1_0 224             // first tid of recurrent-GEMV half
#define COMM0 448            // first tid of comm warp (warp 14)

typedef unsigned long long ull;

__device__ float    g_hbuf[2][NG][NSLOT][HN * BT];
__device__ unsigned g_prod[2][NG];
__device__ unsigned g_cons[2][NG];

__device__ __forceinline__ unsigned ld_acq(const unsigned* p) {
    unsigned v;
    asm volatile("ld.global.acquire.gpu.u32 %0, [%1];" : "=r"(v) : "l"(p));
    return v;
}
__device__ __forceinline__ void st_rel(unsigned* p, unsigned v) {
    asm volatile("st.global.release.gpu.u32 [%0], %1;" :: "l"(p), "r"(v));
}
__device__ __forceinline__ void wait_ge(unsigned* p, unsigned v) {
    if (ld_acq(p) >= v) return;
    while (ld_acq(p) < v) __nanosleep(32);
}
__device__ __forceinline__ float ldcg(const float* p) {
    float v;
    asm volatile("ld.global.cg.f32 %0, [%1];" : "=f"(v) : "l"(p));
    return v;
}
__device__ __forceinline__ ull ffma2(ull a, ull b, ull c) {
    ull d;
    asm("fma.rn.f32x2 %0, %1, %2, %3;" : "=l"(d) : "l"(a), "l"(b), "l"(c));
    return d;
}
__device__ __forceinline__ ull splat2(float x) {
    ull d; unsigned u = __float_as_uint(x);
    asm("mov.b64 %0, {%1, %2};" : "=l"(d) : "r"(u), "r"(u));
    return d;
}
__device__ __forceinline__ float sigf(float x) {
    return __fdividef(1.f, 1.f + __expf(-x));
}
__device__ __forceinline__ float tanhfast(float x) {
    return 2.f * __fdividef(1.f, 1.f + __expf(-2.f * x)) - 1.f;
}

__global__ void __launch_bounds__(64, 1) reset_kernel() {
    int i = threadIdx.x;
    if (i < NG) {
        g_prod[0][i] = 0; g_prod[1][i] = 0;
        g_cons[0][i] = 0; g_cons[1][i] = 0;
    }
}

__global__ void __launch_bounds__(NTH, 1) lstm_kernel(
    const float* __restrict__ x,    const float* __restrict__ Wih1,
    const float* __restrict__ Whh1, const float* __restrict__ bih1,
    const float* __restrict__ bhh1, const float* __restrict__ Wih,
    const float* __restrict__ Whh,  const float* __restrict__ bih,
    const float* __restrict__ bhh,  const float* __restrict__ Wl,
    const float* __restrict__ bl,   float* __restrict__ out)
{
    __shared__ __align__(16) float xin[XBUF][HN * BT];  // layer-input slots
    __shared__ __align__(16) float h_t[HN * BT];        // [k][b]
    __shared__ __align__(16) float c_s[HN * BT];
    __shared__ __align__(16) float gates0[NJ * BT];     // input-GEMV half (+bias)
    __shared__ __align__(16) float gates1[NJ * BT];     // recurrent-GEMV half
    __shared__ __align__(16) float xchunk[32 * BT];     // [q][b], L1 raw-x prefetch
    __shared__ float wl_s[52];

    const int tid  = threadIdx.x;
    const int role = blockIdx.x / NG;   // 0=L1, 1=L2, 2=L3
    const int g    = blockIdx.x % NG;

    const bool is_p0   = (tid < P1_0);                  // warps 0-6
    const bool is_comm = (tid >= COMM0);                // warp 14
    const int  jraw    = is_p0 ? tid : (tid - P1_0);    // row index within half
    const bool active  = (!is_comm) && (jraw < NJ);
    const int  j       = active ? jraw : 0;             // clamped

    // ---------------- per-thread register weights ----------------
    float w_r[HN];
    ull bias2 = 0, w1_2 = 0;
    if (active) {
        if (role == 0) {
            if (is_p0) {
                bias2 = splat2(bih1[j] + bhh1[j]);
                w1_2  = splat2(Wih1[j]);
            } else {
                #pragma unroll
                for (int k = 0; k < HN; k++) w_r[k] = Whh1[j * HN + k];
            }
        } else {
            const int l = role - 1;
            if (is_p0) {
                #pragma unroll
                for (int k = 0; k < HN; k++) w_r[k] = Wih[(l * NJ + j) * HN + k];
                bias2 = splat2(bih[l * NJ + j] + bhh[l * NJ + j]);
            } else {
                #pragma unroll
                for (int k = 0; k < HN; k++) w_r[k] = Whh[(l * NJ + j) * HN + k];
            }
        }
    }
    if (role == 2 && tid < HN) wl_s[tid] = Wl[tid];
    const float blv = (role == 2) ? bl[0] : 0.f;
    for (int i = tid; i < HN * BT; i += NTH) { h_t[i] = 0.f; c_s[i] = 0.f; }
    __syncthreads();

    float*       ring_out = (role < 2) ? &g_hbuf[role][g][0][0]     : (float*)0;
    const float* ring_in  = (role > 0) ? &g_hbuf[role - 1][g][0][0] : (const float*)0;

    // ---- prologue: comm warp prefetches slots 0..DPRE-1, forcing a 4-step
    //      producer lead that persists through the whole run ----
    if (role > 0 && is_comm) {
        for (int d = 0; d < DPRE; d++) {
            if (tid == COMM0) wait_ge(&g_prod[role - 1][g], (unsigned)(d + 1));
            __syncwarp();
            const float* src = ring_in + (d & (NSLOT - 1)) * HN * BT;
            float* dst = xin[d & (XBUF - 1)];
            for (int i = tid - COMM0; i < HN * BT; i += 32) dst[i] = ldcg(src + i);
            __syncwarp();
            if (tid == COMM0) st_rel(&g_cons[role - 1][g], (unsigned)(d + 1));
        }
    }
    __syncthreads();

    for (int t = 0; t < TN; t++) {
        // ---- L1: refill 32-step x chunk (coalesced), transposed [q][b] ----
        if (role == 0 && (t & 31) == 0) {
            if (tid < 256) {
                int b = tid >> 5, q = tid & 31;
                xchunk[q * BT + b] = x[(size_t)(g * BT + b) * TN + t + q];
            }
            __syncthreads();
        }

        // ================= P0: half-GEMVs (warp-split) + comm =================
        if (!is_comm) {
            ull a0, a1, a2, a3;
            if (is_p0) {
                a0 = bias2; a1 = bias2; a2 = bias2; a3 = bias2;
                if (role == 0) {
                    const ulonglong2* xp = (const ulonglong2*)&xchunk[(t & 31) * BT];
                    ulonglong2 X0 = xp[0], X1 = xp[1];
                    a0 = ffma2(X0.x, w1_2, a0); a1 = ffma2(X0.y, w1_2, a1);
                    a2 = ffma2(X1.x, w1_2, a2); a3 = ffma2(X1.y, w1_2, a3);
                } else {
                    const ulonglong2* xp = (const ulonglong2*)&xin[t & (XBUF - 1)][0];
                    #pragma unroll
                    for (int k = 0; k < HN; k++) {
                        ulonglong2 X0 = xp[2 * k], X1 = xp[2 * k + 1];
                        ull w2 = splat2(w_r[k]);
                        a0 = ffma2(X0.x, w2, a0); a1 = ffma2(X0.y, w2, a1);
                        a2 = ffma2(X1.x, w2, a2); a3 = ffma2(X1.y, w2, a3);
                    }
                }
                if (active) {
                    ulonglong2* gp = (ulonglong2*)gates0;
                    ulonglong2 s0; s0.x = a0; s0.y = a1;
                    ulonglong2 s1; s1.x = a2; s1.y = a3;
                    gp[j * 2 + 0] = s0;
                    gp[j * 2 + 1] = s1;
                }
            } else {
                a0 = 0; a1 = 0; a2 = 0; a3 = 0;
                const ulonglong2* hp = (const ulonglong2*)h_t;
                #pragma unroll
                for (int k = 0; k < HN; k++) {
                    ulonglong2 H0 = hp[2 * k], H1 = hp[2 * k + 1];
                    ull w2 = splat2(w_r[k]);
                    a0 = ffma2(H0.x, w2, a0); a1 = ffma2(H0.y, w2, a1);
                    a2 = ffma2(H1.x, w2, a2); a3 = ffma2(H1.y, w2, a3);
                }
                if (active) {
                    ulonglong2* gp = (ulonglong2*)gates1;
                    ulonglong2 s0; s0.x = a0; s0.y = a1;
                    ulonglong2 s1; s1.x = a2; s1.y = a3;
                    gp[j * 2 + 0] = s0;
                    gp[j * 2 + 1] = s1;
                }
            }
        } else {
            // comm warp: prefetch xin(t+DPRE), backpressure, (L3) output proj
            if (role > 0 && t + DPRE < TN) {
                if (tid == COMM0) wait_ge(&g_prod[role - 1][g], (unsigned)(t + DPRE + 1));
                __syncwarp();
                const float* src = ring_in + ((t + DPRE) & (NSLOT - 1)) * HN * BT;
                float* dst = xin[(t + DPRE) & (XBUF - 1)];
                for (int i = tid - COMM0; i < HN * BT; i += 32) dst[i] = ldcg(src + i);
                __syncwarp();
                if (tid == COMM0) st_rel(&g_cons[role - 1][g], (unsigned)(t + DPRE + 1));
            }
            if (role < 2 && t >= NSLOT && tid == COMM0)
                wait_ge(&g_cons[role][g], (unsigned)(t - (NSLOT - 1)));
            if (role == 2 && t > 0) {
                int b = tid - COMM0;
                if (b < BT) {
                    float a = blv;
                    #pragma unroll
                    for (int u = 0; u < HN; u++) a += h_t[u * BT + b] * wl_s[u];
                    out[(size_t)(g * BT + b) * TN + (t - 1)] = a;
                }
            }
        }
        __syncthreads();   // gates ready; h_t free; xin(t+DPRE) landed

        // ================= P1: cell update (sum the two halves) =================
        if (tid < HN * BT) {
            const int i = tid;
            float gi = gates0[i]            + gates1[i];
            float gf = gates0[HN*BT + i]    + gates1[HN*BT + i];
            float gg = gates0[2*HN*BT + i]  + gates1[2*HN*BT + i];
            float go = gates0[3*HN*BT + i]  + gates1[3*HN*BT + i];
            float c  = sigf(gf) * c_s[i] + sigf(gi) * tanhfast(gg);
            float h  = sigf(go) * tanhfast(c);
            c_s[i] = c;
            h_t[i] = h;
            if (role < 2) ring_out[(t & (NSLOT - 1)) * HN * BT + i] = h;
        }
        __syncthreads();   // h_t / ring slot complete
        if (role < 2 && tid == 0) st_rel(&g_prod[role][g], (unsigned)(t + 1));
    }

    // epilogue: out for t = TN-1 (from final h_t of layer 3)
    if (role == 2 && tid < BT) {
        float a = blv;
        #pragma unroll
        for (int u = 0; u < HN; u++) a += h_t[u * BT + tid] * wl_s[u];
        out[(size_t)(g * BT + tid) * TN + (TN - 1)] = a;
    }
}

extern "C" void kernel_launch(void* const* d_in, const int* in_sizes, int n_in,
                              void* d_out, int out_size)
{
    (void)in_sizes; (void)n_in; (void)out_size;
    const float* x    = (const float*)d_in[0];
    const float* Wih1 = (const float*)d_in[1];
    const float* Whh1 = (const float*)d_in[2];
    const float* bih1 = (const float*)d_in[3];
    const float* bhh1 = (const float*)d_in[4];
    const float* Wih  = (const float*)d_in[5];
    const float* Whh  = (const float*)d_in[6];
    const float* bih  = (const float*)d_in[7];
    const float* bhh  = (const float*)d_in[8];
    const float* Wl   = (const float*)d_in[9];
    const float* bl   = (const float*)d_in[10];
    float* out = (float*)d_out;

    reset_kernel<<<1, 64>>>();
    lstm_kernel<<<3 * NG, NTH>>>(x, Wih1, Whh1, bih1, bhh1,
                                 Wih, Whh, bih, bhh, Wl, bl, out);
}